// round 15
// baseline (speedup 1.0000x reference)
#include <cuda_runtime.h>
#include <math.h>

#define EPSJ 1e-6f
#define NB   2000
#define DIM  4000
#define DIMP 4096
#define NE   6000
#define LDA  4128
#define NTHREADS 512
#define NWARPS   (NTHREADS / 32)
#define NFACT 1               /* steps that factor J; rest reuse the LU */

__device__ float d_J[(size_t)DIMP * LDA];
__device__ float d_x[DIMP];
__device__ float d_y[DIMP];
__device__ float d_Pacc[NB];
__device__ float d_Qacc[NB];
__device__ float d_kp[NB];
__device__ float d_kq[NB];
__device__ float d_Uinv[32][128 * 128];
__device__ float d_Linv[32][128 * 128];
__device__ volatile unsigned d_bar_gen;
__device__ volatile unsigned d_arrive[1024];
__device__ volatile unsigned d_rowflag[64];
__device__ volatile unsigned d_colflag[64];
__device__ unsigned d_ticket[64];

struct Params {
    const float* x_in; const int* ei;
    const float *br_r, *br_x, *g_fr, *b_fr, *g_to, *b_to, *tap, *shift;
    const float *p_spec, *q_spec, *gs, *bs;
    const int* bt; const float* vmset;
    float* out;
};

struct SM {
    union {
        struct { float s[64][65]; } diag;
        struct { float su[64][65]; float sa[64][65]; float sinv[64]; } trsm;
        struct { float As[2][16][132]; float Bs[2][16][132]; } gemm;
        struct { float A[64][65]; float B[64][132]; } g64;
        struct { float m[128][129]; float x2[128][129]; float val[128]; float yc[256]; } sub;
    };
};
#define SMEM_BYTES sizeof(SM)

/* ---------- f32x2 packed-FMA helpers ---------- */
__device__ __forceinline__ unsigned long long pk2(float x)
{
    unsigned long long r;
    asm("mov.b64 %0, {%1, %1};" : "=l"(r) : "f"(x));
    return r;
}
__device__ __forceinline__ void fma2(unsigned long long& d,
                                     unsigned long long a, unsigned long long b)
{
    asm("fma.rn.f32x2 %0, %1, %2, %0;" : "+l"(d) : "l"(a), "l"(b));
}
__device__ __forceinline__ float2 upk(unsigned long long v)
{
    float lo, hi;
    asm("mov.b64 {%0, %1}, %2;" : "=f"(lo), "=f"(hi) : "l"(v));
    return make_float2(lo, hi);
}

/* ---------- flag-array grid barrier ---------- */
__device__ __forceinline__ void gsync(unsigned gen)
{
    __syncthreads();
    if (blockIdx.x == 0) {
        __threadfence();
        for (int b = threadIdx.x + 1; b < (int)gridDim.x; b += NTHREADS)
            while (d_arrive[b] != gen) { }
        __threadfence();
        __syncthreads();
        if (threadIdx.x == 0) d_bar_gen = gen;
    } else {
        if (threadIdx.x == 0) {
            __threadfence();
            d_arrive[blockIdx.x] = gen;
            while (d_bar_gen != gen) { }
            __threadfence();
        }
    }
    __syncthreads();
}

__device__ __forceinline__ void wait_flag(volatile unsigned* f, unsigned epoch)
{
    while (*f != epoch) { }
}

/* ---------- LU 64x64 diagonal factor (no pivot) + in-tile y solve ---------- */
__device__ void lu_diag(int k, SM* sm)
{
    float (*s)[65] = sm->diag.s;
    int tid = threadIdx.x;
    __syncthreads();
    for (int idx = tid; idx < 4096; idx += NTHREADS)
        s[idx >> 6][idx & 63] = d_J[(size_t)(k + (idx >> 6)) * LDA + k + (idx & 63)];
    if (tid < 64) s[tid][64] = d_y[k + tid];
    __syncthreads();
    int i = tid & 63, cgp = tid >> 6;
    for (int j = 0; j < 64; j++) {
        float lij = (i > j) ? s[i][j] * (1.f / s[j][j]) : 0.f;
        if (i > j)
            for (int c = cgp; c < 65; c += NTHREADS / 64)
                if (c > j) s[i][c] -= lij * s[j][c];
        __syncthreads();
    }
    for (int idx = tid; idx < 4096; idx += NTHREADS) {
        int r = idx >> 6, c = idx & 63;
        float v = s[r][c];
        if (r > c) v *= (1.f / s[c][c]);
        d_J[(size_t)(k + r) * LDA + k + c] = v;
    }
    if (tid < 64) d_y[k + tid] = s[tid][64];
}

/* ---------- L21 tile = A21 * U11^{-1} ---------- */
__device__ void trsm_row(int k, int r0, SM* sm)
{
    float (*su)[65] = sm->trsm.su;
    float (*sa)[65] = sm->trsm.sa;
    float* sinv = sm->trsm.sinv;
    int tid = threadIdx.x;
    __syncthreads();
    for (int idx = tid; idx < 4096; idx += NTHREADS) {
        int i = idx >> 6, j = idx & 63;
        su[i][j] = d_J[(size_t)(k + i) * LDA + k + j];
        sa[i][j] = d_J[(size_t)(r0 + i) * LDA + k + j];
    }
    __syncthreads();
    if (tid < 64) sinv[tid] = 1.f / su[tid][tid];
    __syncthreads();
    for (int idx = tid; idx < 4096; idx += NTHREADS)
        su[idx >> 6][idx & 63] *= sinv[idx >> 6];
    __syncthreads();
    int i = tid & 63, cgp = tid >> 6;
    for (int j = 0; j < 64; j++) {
        float aij = sa[i][j];
        for (int c = cgp; c < 64; c += NTHREADS / 64)
            if (c > j) sa[i][c] -= aij * su[j][c];
        __syncthreads();
    }
    for (int idx = tid; idx < 4096; idx += NTHREADS) {
        int r = idx >> 6, j = idx & 63;
        d_J[(size_t)(r0 + r) * LDA + k + j] = sa[r][j] * sinv[j];
    }
}

/* ---------- U12 tile = L11^{-1} * A12 ---------- */
__device__ void trsm_col(int k, int c0, SM* sm)
{
    float (*sl)[65] = sm->trsm.su;
    float (*sa)[65] = sm->trsm.sa;
    int tid = threadIdx.x;
    __syncthreads();
    for (int idx = tid; idx < 4096; idx += NTHREADS) {
        int i = idx >> 6, j = idx & 63;
        sl[i][j] = d_J[(size_t)(k + i) * LDA + k + j];
        sa[i][j] = d_J[(size_t)(k + i) * LDA + c0 + j];
    }
    __syncthreads();
    int c = tid & 63, rg = tid >> 6;
    for (int j = 0; j < 64; j++) {
        float ajc = sa[j][c];
        for (int i2 = rg; i2 < 64; i2 += NTHREADS / 64)
            if (i2 > j) sa[i2][c] -= sl[i2][j] * ajc;
        __syncthreads();
    }
    for (int idx = tid; idx < 4096; idx += NTHREADS)
        d_J[(size_t)(k + (idx >> 6)) * LDA + c0 + (idx & 63)] = sa[idx >> 6][idx & 63];
}

/* ---------- small trailing tile: 64 rows x NCOLS cols, K=64 ---------- */
template <int NCOLS>
__device__ void gemm_block64(int k, int row0, int col0, SM* sm)
{
    const int tid = threadIdx.x;
    float (*A)[65]  = sm->g64.A;
    float (*B)[132] = sm->g64.B;
    __syncthreads();
    for (int idx = tid; idx < 4096; idx += NTHREADS) {
        int r = idx >> 6, c = idx & 63;
        A[c][r] = d_J[(size_t)(k + 64 + row0 + r) * LDA + k + c];
    }
    for (int idx = tid; idx < 64 * NCOLS; idx += NTHREADS) {
        int kk = idx / NCOLS, c = idx % NCOLS;
        B[kk][c] = d_J[(size_t)(k + kk) * LDA + (k + 64 + col0 + c)];
    }
    __syncthreads();
    constexpr int W = NCOLS / 16;
    const int rp = (tid >> 4) * 2;
    const int ct = (tid & 15) * W;
    float acc0[W], acc1[W];
#pragma unroll
    for (int v = 0; v < W; v++) { acc0[v] = 0.f; acc1[v] = 0.f; }
    for (int kk = 0; kk < 64; kk++) {
        float a0 = A[kk][rp], a1 = A[kk][rp + 1];
#pragma unroll
        for (int v = 0; v < W; v++) {
            float b = B[kk][ct + v];
            acc0[v] += a0 * b;
            acc1[v] += a1 * b;
        }
    }
    size_t base = (size_t)(k + 64 + row0 + rp) * LDA + (k + 64 + col0 + ct);
#pragma unroll
    for (int v = 0; v < W; v++) {
        d_J[base + v]       -= acc0[v];
        d_J[base + LDA + v] -= acc1[v];
    }
}

/* ---------- trailing update tile: 128x128, K=64, f32x2, double-buffered ---------- */
__device__ void gemm_tile(int k, int m, int row0, int col0, SM* sm)
{
    const int k2 = k + 64;
    const int tid = threadIdx.x;
    const int ty = tid >> 5;
    const int tx = tid & 31;
    const int ai = tid >> 2;
    const int aj = (tid & 3) << 2;
    const int bk = tid >> 5;
    const int bc = (tid & 31) << 2;
    const bool arow_ok = (row0 + ai) < m;
    const bool bcol_ok = (col0 + bc) < m;
    const float* gA = &d_J[(size_t)(k2 + row0 + ai) * LDA + k + aj];
    const float* gB = &d_J[(size_t)(k + bk) * LDA + k2 + col0 + bc];

    unsigned long long acc[4][4];
#pragma unroll
    for (int u = 0; u < 4; u++)
#pragma unroll
        for (int v = 0; v < 4; v++) acc[u][v] = 0ull;

    float4 z4 = make_float4(0.f, 0.f, 0.f, 0.f);
    float4 ra = arow_ok ? *(const float4*)gA : z4;
    float4 rb = bcol_ok ? *(const float4*)gB : z4;

    __syncthreads();
    sm->gemm.As[0][aj + 0][ai] = ra.x;
    sm->gemm.As[0][aj + 1][ai] = ra.y;
    sm->gemm.As[0][aj + 2][ai] = ra.z;
    sm->gemm.As[0][aj + 3][ai] = ra.w;
    *(float4*)&sm->gemm.Bs[0][bk][bc] = rb;
    __syncthreads();

    for (int c = 0; c < 4; c++) {
        const int cur = c & 1;
        float4 na, nb;
        if (c < 3) {
            na = arow_ok ? *(const float4*)(gA + (c + 1) * 16) : z4;
            nb = bcol_ok ? *(const float4*)(gB + (size_t)(c + 1) * 16 * LDA) : z4;
        }
#pragma unroll
        for (int kk = 0; kk < 16; kk++) {
            const unsigned long long* ap =
                (const unsigned long long*)&sm->gemm.As[cur][kk][ty * 8];
            unsigned long long a0 = ap[0], a1 = ap[1], a2 = ap[2], a3 = ap[3];
            float4 bv = *(const float4*)&sm->gemm.Bs[cur][kk][tx * 4];
            unsigned long long b0 = pk2(bv.x), b1 = pk2(bv.y),
                               b2 = pk2(bv.z), b3 = pk2(bv.w);
            fma2(acc[0][0], a0, b0); fma2(acc[0][1], a0, b1);
            fma2(acc[0][2], a0, b2); fma2(acc[0][3], a0, b3);
            fma2(acc[1][0], a1, b0); fma2(acc[1][1], a1, b1);
            fma2(acc[1][2], a1, b2); fma2(acc[1][3], a1, b3);
            fma2(acc[2][0], a2, b0); fma2(acc[2][1], a2, b1);
            fma2(acc[2][2], a2, b2); fma2(acc[2][3], a2, b3);
            fma2(acc[3][0], a3, b0); fma2(acc[3][1], a3, b1);
            fma2(acc[3][2], a3, b2); fma2(acc[3][3], a3, b3);
        }
        if (c < 3) {
            const int nxt = cur ^ 1;
            sm->gemm.As[nxt][aj + 0][ai] = na.x;
            sm->gemm.As[nxt][aj + 1][ai] = na.y;
            sm->gemm.As[nxt][aj + 2][ai] = na.z;
            sm->gemm.As[nxt][aj + 3][ai] = na.w;
            *(float4*)&sm->gemm.Bs[nxt][bk][bc] = nb;
        }
        __syncthreads();
    }

#pragma unroll
    for (int u = 0; u < 4; u++) {
        int r0 = row0 + ty * 8 + u * 2;
        if (r0 < m && (col0 + tx * 4) < m) {
            float2 p0 = upk(acc[u][0]), p1 = upk(acc[u][1]);
            float2 p2 = upk(acc[u][2]), p3 = upk(acc[u][3]);
            float4* c0 = (float4*)&d_J[(size_t)(k2 + r0) * LDA + k2 + col0 + tx * 4];
            float4 v0 = *c0;
            v0.x -= p0.x; v0.y -= p1.x; v0.z -= p2.x; v0.w -= p3.x;
            *c0 = v0;
            float4* c1 = (float4*)&d_J[(size_t)(k2 + r0 + 1) * LDA + k2 + col0 + tx * 4];
            float4 v1 = *c1;
            v1.x -= p0.y; v1.y -= p1.y; v1.z -= p2.y; v1.w -= p3.y;
            *c1 = v1;
        }
    }
}

/* ---------- forward y-update: y[r0..r1) -= L21(rows) . y_k (64-wide) ---------- */
__device__ __forceinline__ void y_update_range(int k, int r0, int r1)
{
    const int warp = threadIdx.x >> 5, lane = threadIdx.x & 31;
    const float ylo = d_y[k + lane];
    const float yhi = d_y[k + 32 + lane];
    for (int r = r0 + warp; r < r1; r += NWARPS) {
        const float* row = &d_J[(size_t)r * LDA + k];
        float s = row[lane] * ylo + row[lane + 32] * yhi;
#pragma unroll
        for (int o = 16; o; o >>= 1) s += __shfl_down_sync(0xffffffffu, s, o);
        if (lane == 0) d_y[r] -= s;
    }
}

/* ---------- invert 128x128 U diag block -> d_Uinv[bi] ---------- */
__device__ void invert_u128(int bi, SM* sm)
{
    const int k = bi * 128;
    float (*U)[129] = sm->sub.m;
    float (*X)[129] = sm->sub.x2;
    const int t = threadIdx.x;
    __syncthreads();
    for (int idx = t; idx < 128 * 128; idx += NTHREADS) {
        U[idx >> 7][idx & 127] = d_J[(size_t)(k + (idx >> 7)) * LDA + k + (idx & 127)];
        X[idx >> 7][idx & 127] = 0.f;
    }
    __syncthreads();
    if (t < 128) {
        int c = t;
        X[c][c] = 1.f / U[c][c];
        for (int j = c - 1; j >= 0; j--) {
            float acc = 0.f;
#pragma unroll 4
            for (int i = j + 1; i <= c; i++) acc += U[j][i] * X[i][c];
            X[j][c] = -acc / U[j][j];
        }
    }
    __syncthreads();
    for (int idx = t; idx < 128 * 128; idx += NTHREADS)
        d_Uinv[bi][idx] = X[idx >> 7][idx & 127];
    __syncthreads();
}

/* ---------- invert 128x128 unit-L diag block -> d_Linv[bi] ---------- */
__device__ void invert_l128(int bi, SM* sm)
{
    const int k = bi * 128;
    float (*L)[129] = sm->sub.m;
    float (*X)[129] = sm->sub.x2;
    const int t = threadIdx.x;
    __syncthreads();
    for (int idx = t; idx < 128 * 128; idx += NTHREADS) {
        L[idx >> 7][idx & 127] = d_J[(size_t)(k + (idx >> 7)) * LDA + k + (idx & 127)];
        X[idx >> 7][idx & 127] = 0.f;
    }
    __syncthreads();
    if (t < 128) {
        int c = t;
        X[c][c] = 1.f;
        for (int j = c + 1; j < 128; j++) {
            float acc = 0.f;
#pragma unroll 4
            for (int i = c; i < j; i++) acc += L[j][i] * X[i][c];
            X[j][c] = -acc;
        }
    }
    __syncthreads();
    for (int idx = t; idx < 128 * 128; idx += NTHREADS)
        d_Linv[bi][idx] = X[idx >> 7][idx & 127];
    __syncthreads();
}

/* ---------- y[k..k+128) = M * y[k..k+128), M dense 128x128 in global ---------- */
__device__ void apply_inv_gl(const float* __restrict__ M, int k, SM* sm)
{
    const int t = threadIdx.x, warp = t >> 5, lane = t & 31;
    __syncthreads();
    if (t < 128) sm->sub.val[t] = d_y[k + t];
    __syncthreads();
    float res[8];
#pragma unroll
    for (int rr = 0; rr < 8; rr++) {
        int r = warp * 8 + rr;
        const float* row = &M[r * 128];
        float s = row[lane] * sm->sub.val[lane]
                + row[lane + 32] * sm->sub.val[lane + 32]
                + row[lane + 64] * sm->sub.val[lane + 64]
                + row[lane + 96] * sm->sub.val[lane + 96];
#pragma unroll
        for (int o = 16; o; o >>= 1) s += __shfl_down_sync(0xffffffffu, s, o);
        res[rr] = s;
    }
    __syncthreads();
    if (lane == 0)
#pragma unroll
        for (int rr = 0; rr < 8; rr++) d_y[k + warp * 8 + rr] = res[rr];
    __syncthreads();
}

/* ---------- row dots ---------- */
__device__ __forceinline__ void row_update(int r, int k, const float* yc, int lane)
{
    const float* row = &d_J[(size_t)r * LDA + k];
    float s = row[lane] * yc[lane] + row[lane + 32] * yc[lane + 32]
            + row[lane + 64] * yc[lane + 64] + row[lane + 96] * yc[lane + 96];
#pragma unroll
    for (int o = 16; o; o >>= 1) s += __shfl_down_sync(0xffffffffu, s, o);
    if (lane == 0) d_y[r] -= s;
}

__device__ __forceinline__ void row_update256(int r, int k, const float* yc, int lane)
{
    const float* row = &d_J[(size_t)r * LDA + k];
    float s = 0.f;
#pragma unroll
    for (int o = 0; o < 256; o += 32) s += row[lane + o] * yc[lane + o];
#pragma unroll
    for (int o = 16; o; o >>= 1) s += __shfl_down_sync(0xffffffffu, s, o);
    if (lane == 0) d_y[r] -= s;
}

/* ---------- block-0 super-panel finalizers (256 rows) ---------- */
__device__ void fwd_finalize256(int ks, SM* sm)
{
    const int tid = threadIdx.x, warp = tid >> 5, lane = tid & 31;
    apply_inv_gl(d_Linv[ks >> 7], ks, sm);           /* y_lo final */
    if (tid < 128) sm->sub.yc[tid] = d_y[ks + tid];
    __syncthreads();
    for (int r = ks + 128 + warp; r < ks + 256; r += NWARPS)
        row_update(r, ks, sm->sub.yc, lane);
    __syncthreads();
    apply_inv_gl(d_Linv[(ks >> 7) + 1], ks + 128, sm); /* y_hi final */
}

__device__ void bwd_finalize256(int ks, SM* sm)
{
    const int tid = threadIdx.x, warp = tid >> 5, lane = tid & 31;
    apply_inv_gl(d_Uinv[(ks >> 7) + 1], ks + 128, sm); /* y_hi final */
    if (tid < 128) sm->sub.yc[tid] = d_y[ks + 128 + tid];
    __syncthreads();
    for (int r = ks + warp; r < ks + 128; r += NWARPS)
        row_update(r, ks + 128, sm->sub.yc, lane);
    __syncthreads();
    apply_inv_gl(d_Uinv[ks >> 7], ks, sm);             /* y_lo final */
}

/* ---------- RHS value for row i ---------- */
__device__ __forceinline__ float rhs_val(const Params& P, int i)
{
    if (i < NB) {
        float vm = d_x[NB + i];
        return (P.bt[i] == 3) ? d_x[i]
                              : (P.p_spec[i] - (d_Pacc[i] + vm * vm * P.gs[i]));
    } else if (i < DIM) {
        int ib = i - NB;
        float vm = d_x[i];
        return (P.bt[ib] >= 2) ? (vm - P.vmset[ib])
                               : (P.q_spec[ib] - (d_Qacc[ib] - vm * vm * P.bs[ib]));
    }
    return 0.f;
}

#define GSYNC() do { gen++; gsync(gen); } while (0)

/* =======================================================================
 *  The one persistent kernel
 * ======================================================================= */
__global__ void __launch_bounds__(NTHREADS, 1) solver_kernel(Params P)
{
    extern __shared__ char s_raw[];
    SM* sm = (SM*)s_raw;
    __shared__ int s_job;
    const int tid = threadIdx.x;
    const int gsize = gridDim.x * NTHREADS;
    const int gtid = blockIdx.x * NTHREADS + tid;
    const int warp = tid >> 5, lane = tid & 31;
    unsigned gen = 0;

    for (int i = gtid; i < DIMP; i += gsize) {
        d_x[i] = (i < DIM) ? P.x_in[i] : 0.0f;
        if (i < NB) {
            int b = P.bt[i];
            d_kp[i] = (b == 3) ? 0.f : 1.f;
            d_kq[i] = (b >= 2) ? 0.f : 1.f;
        }
        if (i < 64) { d_rowflag[i] = 0u; d_colflag[i] = 0u; d_ticket[i] = 0u; }
    }
    {
        size_t tot = (size_t)DIMP * LDA / 4;
        float4 z = make_float4(0.f, 0.f, 0.f, 0.f);
        for (size_t i = gtid; i < tot; i += gsize) ((float4*)d_J)[i] = z;
        for (int i = gtid; i < NB; i += gsize) { d_Pacc[i] = 0.f; d_Qacc[i] = 0.f; }
    }
    GSYNC();

    for (int t5 = 0; t5 < 5; t5++) {
        const bool do_factor = (t5 < NFACT);

        if (do_factor) {
            /* ---- assembly: edges (flows + J) + diag adds + padding ---- */
            for (int e = gtid; e < NE; e += gsize) {
                int s = P.ei[e], d = P.ei[NE + e];
                float vm_s = d_x[NB + s], vm_d = d_x[NB + d];
                float r = P.br_r[e], xx = P.br_x[e];
                float den = r * r + xx * xx;
                float g = r / den, b = -xx / den;
                float tp = P.tap[e];
                float th = d_x[s] - d_x[d];
                float sf, cf;
                sincosf(th - P.shift[e], &sf, &cf);
                float ct = cf, st = -sf;
                float vi_t = vm_s / tp;
                float vij = vm_s * vm_d / tp;

                float gfr = P.g_fr[e], bfr = P.b_fr[e], gto = P.g_to[e], bto = P.b_to[e];
                float Pf = vi_t * vi_t * (g + gfr) + vij * (-g * cf - b * sf);
                float Qf = -vi_t * vi_t * (b + bfr) + vij * (-g * sf + b * cf);
                float Pt = vm_d * vm_d * (g + gto) + vij * (-g * ct - b * st);
                float Qt = -vm_d * vm_d * (b + bto) + vij * (-g * st + b * ct);
                atomicAdd(&d_Pacc[s], Pf); atomicAdd(&d_Pacc[d], Pt);
                atomicAdd(&d_Qacc[s], Qf); atomicAdd(&d_Qacc[d], Qt);

                float Af = g * cf + b * sf, Bf = g * sf - b * cf;
                float At = g * ct + b * st, Bt = g * st - b * ct;
                size_t Rs  = (size_t)s * LDA, Rd = (size_t)d * LDA;
                size_t Rqs = (size_t)(NB + s) * LDA, Rqd = (size_t)(NB + d) * LDA;

                if (d_kp[s] != 0.f) {
                    atomicAdd(&d_J[Rs + s],      -vij * Bf);
                    atomicAdd(&d_J[Rs + d],       vij * Bf);
                    atomicAdd(&d_J[Rs + NB + s], -(2.f * vm_s / (tp * tp) * (g + gfr) - vm_d / tp * Af));
                    atomicAdd(&d_J[Rs + NB + d],  (vm_s / tp) * Af);
                }
                if (d_kp[d] != 0.f) {
                    atomicAdd(&d_J[Rd + d],      -vij * Bt);
                    atomicAdd(&d_J[Rd + s],       vij * Bt);
                    atomicAdd(&d_J[Rd + NB + d], -(2.f * vm_d * (g + gto) - vm_s / tp * At));
                    atomicAdd(&d_J[Rd + NB + s],  (vm_d / tp) * At);
                }
                if (d_kq[s] != 0.f) {
                    atomicAdd(&d_J[Rqs + s],      vij * Af);
                    atomicAdd(&d_J[Rqs + d],     -vij * Af);
                    atomicAdd(&d_J[Rqs + NB + s], (2.f * vm_s / (tp * tp) * (b + bfr) + vm_d / tp * Bf));
                    atomicAdd(&d_J[Rqs + NB + d], (vm_s / tp) * Bf);
                }
                if (d_kq[d] != 0.f) {
                    atomicAdd(&d_J[Rqd + d],      vij * At);
                    atomicAdd(&d_J[Rqd + s],     -vij * At);
                    atomicAdd(&d_J[Rqd + NB + d], (2.f * vm_d * (b + bto) + vm_s / tp * Bt));
                    atomicAdd(&d_J[Rqd + NB + s], (vm_s / tp) * Bt);
                }
            }
            for (int i = gtid; i < NB; i += gsize) {
                int b = P.bt[i];
                float vm = d_x[NB + i];
                atomicAdd(&d_J[(size_t)i * LDA + i], ((b == 3) ? 1.f : 0.f) + EPSJ);
                atomicAdd(&d_J[(size_t)i * LDA + NB + i], d_kp[i] * (-2.f * vm * P.gs[i]));
                atomicAdd(&d_J[(size_t)(NB + i) * LDA + (NB + i)],
                          d_kq[i] * (2.f * vm * P.bs[i]) + ((b >= 2) ? 1.f : 0.f) + EPSJ);
            }
            for (int i = DIM + gtid; i < DIMP; i += gsize)
                d_J[(size_t)i * LDA + i] = 1.0f;
            GSYNC();

            /* ---- RHS + lu_diag(0); reset ticket[0] ---- */
            if (blockIdx.x == 0) {
                if (tid == 0) d_ticket[0] = 0u;
                if (tid < 64) d_y[tid] = rhs_val(P, tid);
                __syncthreads();
                lu_diag(0, sm);
            } else {
                for (int i = 64 + (blockIdx.x - 1) * NTHREADS + tid; i < DIMP;
                     i += (gridDim.x - 1) * NTHREADS)
                    d_y[i] = rhs_val(P, i);
            }
            GSYNC();

            /* ---- blocked LU (fwd subst folded), ticket pool ---- */
            for (int k = 0; k + 64 < DIMP; k += 64) {
                const int m = DIMP - k - 64;
                const int ntr = m / 64;
                const int g = (m + 127) / 128;
                const int kp = k >> 6;
                const unsigned epoch = (unsigned)(t5 * 64 + kp + 1);
                const int bid = blockIdx.x;

                if (bid == 0) {
                    if (tid == 0) {
                        d_ticket[kp + 1] = 0u;
                        wait_flag(&d_rowflag[0], epoch);
                        wait_flag(&d_colflag[0], epoch);
                        __threadfence();
                    }
                    __syncthreads();
                    y_update_range(k, k + 64, k + 128);
                    gemm_block64<64>(k, 0, 0, sm);
                    lu_diag(k + 64, sm);
                } else {
                    for (int j = bid - 1; j < 2 * ntr; j += gridDim.x - 1) {
                        if (j < ntr) {
                            trsm_row(k, k + 64 + j * 64, sm);
                            __syncthreads();
                            if (tid == 0) { __threadfence(); d_rowflag[j] = epoch; }
                        } else {
                            int i2 = j - ntr;
                            trsm_col(k, k + 64 + i2 * 64, sm);
                            __syncthreads();
                            if (tid == 0) { __threadfence(); d_colflag[i2] = epoch; }
                        }
                    }
                    const int nq = (m >= 128) ? 2 : 0;
                    const int nyj = ntr - 1;
                    const int njobs = nq + nyj + g * g - 1;
                    for (;;) {
                        __syncthreads();
                        if (tid == 0) s_job = (int)atomicAdd(&d_ticket[kp], 1u);
                        __syncthreads();
                        const int job = s_job;
                        if (job >= njobs) break;
                        if (job < nq) {
                            if (job == 0) {
                                if (tid == 0) {
                                    wait_flag(&d_rowflag[1], epoch);
                                    wait_flag(&d_colflag[0], epoch);
                                    wait_flag(&d_colflag[1], epoch);
                                    __threadfence();
                                }
                                __syncthreads();
                                gemm_block64<128>(k, 64, 0, sm);
                            } else {
                                if (tid == 0) {
                                    wait_flag(&d_rowflag[0], epoch);
                                    wait_flag(&d_colflag[1], epoch);
                                    __threadfence();
                                }
                                __syncthreads();
                                gemm_block64<64>(k, 0, 64, sm);
                            }
                        } else if (job < nq + nyj) {
                            int rt = job - nq + 1;
                            if (tid == 0) { wait_flag(&d_rowflag[rt], epoch); __threadfence(); }
                            __syncthreads();
                            int r0 = k + 64 + rt * 64;
                            y_update_range(k, r0, r0 + 64);
                        } else {
                            int t2 = job - nq - nyj + 1;
                            int r = t2 / g, c = t2 % g;
                            if (tid == 0) {
                                wait_flag(&d_rowflag[2 * r], epoch);
                                if (2 * r + 1 < ntr) wait_flag(&d_rowflag[2 * r + 1], epoch);
                                wait_flag(&d_colflag[2 * c], epoch);
                                if (2 * c + 1 < ntr) wait_flag(&d_colflag[2 * c + 1], epoch);
                                __threadfence();
                            }
                            __syncthreads();
                            gemm_tile(k, m, r * 128, c * 128, sm);
                        }
                    }
                }
                GSYNC();
            }

            /* ---- one-time: invert all 128-diag blocks ---- */
            if (blockIdx.x < 32) invert_u128(blockIdx.x, sm);
            else if (blockIdx.x < 64) invert_l128(blockIdx.x - 32, sm);
            GSYNC();

            /* ---- start backward: finalize last super-panel ---- */
            if (blockIdx.x == 0) bwd_finalize256(DIMP - 256, sm);
            GSYNC();
        } else {
            /* ======== substitution-only step: reuse stored LU ======== */
            for (int e = gtid; e < NE; e += gsize) {
                int s = P.ei[e], d = P.ei[NE + e];
                float vm_s = d_x[NB + s], vm_d = d_x[NB + d];
                float r = P.br_r[e], xx = P.br_x[e];
                float den = r * r + xx * xx;
                float g = r / den, b = -xx / den;
                float tp = P.tap[e];
                float th = d_x[s] - d_x[d];
                float sf, cf;
                sincosf(th - P.shift[e], &sf, &cf);
                float ct = cf, st = -sf;
                float vi_t = vm_s / tp;
                float vij = vm_s * vm_d / tp;
                float Pf = vi_t * vi_t * (g + P.g_fr[e]) + vij * (-g * cf - b * sf);
                float Qf = -vi_t * vi_t * (b + P.b_fr[e]) + vij * (-g * sf + b * cf);
                float Pt = vm_d * vm_d * (g + P.g_to[e]) + vij * (-g * ct - b * st);
                float Qt = -vm_d * vm_d * (b + P.b_to[e]) + vij * (-g * st + b * ct);
                atomicAdd(&d_Pacc[s], Pf); atomicAdd(&d_Pacc[d], Pt);
                atomicAdd(&d_Qacc[s], Qf); atomicAdd(&d_Qacc[d], Qt);
            }
            GSYNC();

            /* RHS + finalize super-panel 0 */
            if (blockIdx.x == 0) {
                for (int i = tid; i < 256; i += NTHREADS) d_y[i] = rhs_val(P, i);
                __syncthreads();
                fwd_finalize256(0, sm);
            } else {
                for (int i = 256 + (blockIdx.x - 1) * NTHREADS + tid; i < DIMP;
                     i += (gridDim.x - 1) * NTHREADS)
                    d_y[i] = rhs_val(P, i);
            }
            GSYNC();

            /* forward sweep: 15 super-panel phases */
            for (int k = 0; k + 512 <= DIMP; k += 256) {
                __syncthreads();
                if (tid < 256) sm->sub.yc[tid] = d_y[k + tid];
                __syncthreads();
                if (blockIdx.x == 0) {
                    for (int r = k + 256 + warp; r < k + 512; r += NWARPS)
                        row_update256(r, k, sm->sub.yc, lane);
                    __syncthreads();
                    fwd_finalize256(k + 256, sm);
                    if (k == DIMP - 512) bwd_finalize256(DIMP - 256, sm);
                } else {
                    int gw = (blockIdx.x - 1) * NWARPS + warp;
                    int tot = (gridDim.x - 1) * NWARPS;
                    for (int r = k + 512 + gw; r < DIMP; r += tot)
                        row_update256(r, k, sm->sub.yc, lane);
                }
                GSYNC();
            }
        }
        /* y[DIMP-256..DIMP) fully solved; backward sweep over 15 super-panels */

        for (int k = DIMP - 256; k >= 256; k -= 256) {
            __syncthreads();
            if (tid < 256) sm->sub.yc[tid] = d_y[k + tid];
            __syncthreads();
            if (blockIdx.x == 0) {
                for (int r = k - 256 + warp; r < k; r += NWARPS)
                    row_update256(r, k, sm->sub.yc, lane);
                __syncthreads();
                bwd_finalize256(k - 256, sm);
            } else {
                int gw = (blockIdx.x - 1) * NWARPS + warp;
                int tot = (gridDim.x - 1) * NWARPS;
                for (int r = gw; r < k - 256; r += tot)
                    row_update256(r, k, sm->sub.yc, lane);
            }
            GSYNC();
        }

        /* ---- Newton update; zero accs; zero J only if next step factors ---- */
        for (int i = gtid; i < DIM; i += gsize) {
            float v = d_x[i] - d_y[i];
            if (i >= NB) v = fminf(fmaxf(v, 0.5f), 1.5f);
            d_x[i] = v;
        }
        if (t5 < 4) {
            for (int i = gtid; i < NB; i += gsize) { d_Pacc[i] = 0.f; d_Qacc[i] = 0.f; }
            if (t5 + 1 < NFACT) {
                size_t tot = (size_t)DIMP * LDA / 4;
                float4 z = make_float4(0.f, 0.f, 0.f, 0.f);
                for (size_t i = gtid; i < tot; i += gsize) ((float4*)d_J)[i] = z;
            }
        }
        GSYNC();
    }

    for (int i = gtid; i < DIM; i += gsize)
        P.out[i] = d_x[i];
}

extern "C" void kernel_launch(void* const* d_in, const int* in_sizes, int n_in,
                              void* d_out, int out_size)
{
    Params P;
    P.x_in   = (const float*)d_in[0];
    P.ei     = (const int*)  d_in[1];
    P.br_r   = (const float*)d_in[2];
    P.br_x   = (const float*)d_in[3];
    P.g_fr   = (const float*)d_in[4];
    P.b_fr   = (const float*)d_in[5];
    P.g_to   = (const float*)d_in[6];
    P.b_to   = (const float*)d_in[7];
    P.tap    = (const float*)d_in[8];
    P.shift  = (const float*)d_in[9];
    P.p_spec = (const float*)d_in[10];
    P.q_spec = (const float*)d_in[11];
    P.gs     = (const float*)d_in[12];
    P.bs     = (const float*)d_in[13];
    P.bt     = (const int*)  d_in[14];
    P.vmset  = (const float*)d_in[15];
    P.out    = (float*)d_out;

    cudaFuncSetAttribute(solver_kernel,
                         cudaFuncAttributeMaxDynamicSharedMemorySize,
                         (int)SMEM_BYTES);

    int dev = 0, nsm = 0, per_sm = 0;
    cudaGetDevice(&dev);
    cudaDeviceGetAttribute(&nsm, cudaDevAttrMultiProcessorCount, dev);
    cudaOccupancyMaxActiveBlocksPerMultiprocessor(&per_sm, solver_kernel,
                                                  NTHREADS, SMEM_BYTES);
    if (per_sm < 1) per_sm = 1;
    int grid = nsm * per_sm;
    if (grid < 64) grid = 64;
    if (grid > 1024) grid = 1024;

    solver_kernel<<<grid, NTHREADS, SMEM_BYTES>>>(P);
}

// round 17
// speedup vs baseline: 1.1450x; 1.1450x over previous
#include <cuda_runtime.h>
#include <math.h>

#define EPSJ 1e-6f
#define NB   2000
#define DIM  4000
#define DIMP 4096
#define NE   6000
#define LDA  4128
#define NTHREADS 512
#define NWARPS   (NTHREADS / 32)
#define PW   128              /* substitution panel width */
#define NFACT 1               /* steps that factor J; rest reuse the LU */
#define TSTEPS 5              /* total quasi-Newton iterations (all required) */

__device__ float d_J[(size_t)DIMP * LDA];
__device__ float d_x[DIMP];
__device__ float d_y[DIMP];
__device__ float d_Pacc[NB];
__device__ float d_Qacc[NB];
__device__ float d_kp[NB];
__device__ float d_kq[NB];
__device__ float d_Uinv[32][128 * 128];   /* per-128-block U diag inverses */
__device__ float d_Linv[32][128 * 128];   /* per-128-block unit-L diag inverses */
__device__ volatile unsigned d_bar_gen;
__device__ volatile unsigned d_arrive[1024];
__device__ volatile unsigned d_rowflag[64];
__device__ volatile unsigned d_colflag[64];
__device__ unsigned d_ticket[64];

struct Params {
    const float* x_in; const int* ei;
    const float *br_r, *br_x, *g_fr, *b_fr, *g_to, *b_to, *tap, *shift;
    const float *p_spec, *q_spec, *gs, *bs;
    const int* bt; const float* vmset;
    float* out;
};

struct SM {
    union {
        struct { float s[64][65]; } diag;
        struct { float su[64][65]; float sa[64][65]; float sinv[64]; } trsm;
        struct { float As[2][16][132]; float Bs[2][16][132]; } gemm;
        struct { float A[64][65]; float B[64][132]; } g64;
        struct { float m[128][129]; float x2[128][129]; float val[128]; float yc[128]; } sub;
    };
};
#define SMEM_BYTES sizeof(SM)

/* ---------- f32x2 packed-FMA helpers ---------- */
__device__ __forceinline__ unsigned long long pk2(float x)
{
    unsigned long long r;
    asm("mov.b64 %0, {%1, %1};" : "=l"(r) : "f"(x));
    return r;
}
__device__ __forceinline__ void fma2(unsigned long long& d,
                                     unsigned long long a, unsigned long long b)
{
    asm("fma.rn.f32x2 %0, %1, %2, %0;" : "+l"(d) : "l"(a), "l"(b));
}
__device__ __forceinline__ float2 upk(unsigned long long v)
{
    float lo, hi;
    asm("mov.b64 {%0, %1}, %2;" : "=f"(lo), "=f"(hi) : "l"(v));
    return make_float2(lo, hi);
}

/* ---------- flag-array grid barrier ---------- */
__device__ __forceinline__ void gsync(unsigned gen)
{
    __syncthreads();
    if (blockIdx.x == 0) {
        __threadfence();
        for (int b = threadIdx.x + 1; b < (int)gridDim.x; b += NTHREADS)
            while (d_arrive[b] != gen) { }
        __threadfence();
        __syncthreads();
        if (threadIdx.x == 0) d_bar_gen = gen;
    } else {
        if (threadIdx.x == 0) {
            __threadfence();
            d_arrive[blockIdx.x] = gen;
            while (d_bar_gen != gen) { }
            __threadfence();
        }
    }
    __syncthreads();
}

__device__ __forceinline__ void wait_flag(volatile unsigned* f, unsigned epoch)
{
    while (*f != epoch) { }
}

/* ---------- LU 64x64 diagonal factor (no pivot) + in-tile y solve ---------- */
__device__ void lu_diag(int k, SM* sm)
{
    float (*s)[65] = sm->diag.s;
    int tid = threadIdx.x;
    __syncthreads();
    for (int idx = tid; idx < 4096; idx += NTHREADS)
        s[idx >> 6][idx & 63] = d_J[(size_t)(k + (idx >> 6)) * LDA + k + (idx & 63)];
    if (tid < 64) s[tid][64] = d_y[k + tid];
    __syncthreads();
    int i = tid & 63, cgp = tid >> 6;
    for (int j = 0; j < 64; j++) {
        float lij = (i > j) ? s[i][j] * (1.f / s[j][j]) : 0.f;
        if (i > j)
            for (int c = cgp; c < 65; c += NTHREADS / 64)
                if (c > j) s[i][c] -= lij * s[j][c];
        __syncthreads();
    }
    for (int idx = tid; idx < 4096; idx += NTHREADS) {
        int r = idx >> 6, c = idx & 63;
        float v = s[r][c];
        if (r > c) v *= (1.f / s[c][c]);
        d_J[(size_t)(k + r) * LDA + k + c] = v;
    }
    if (tid < 64) d_y[k + tid] = s[tid][64];
}

/* ---------- L21 tile = A21 * U11^{-1} ---------- */
__device__ void trsm_row(int k, int r0, SM* sm)
{
    float (*su)[65] = sm->trsm.su;
    float (*sa)[65] = sm->trsm.sa;
    float* sinv = sm->trsm.sinv;
    int tid = threadIdx.x;
    __syncthreads();
    for (int idx = tid; idx < 4096; idx += NTHREADS) {
        int i = idx >> 6, j = idx & 63;
        su[i][j] = d_J[(size_t)(k + i) * LDA + k + j];
        sa[i][j] = d_J[(size_t)(r0 + i) * LDA + k + j];
    }
    __syncthreads();
    if (tid < 64) sinv[tid] = 1.f / su[tid][tid];
    __syncthreads();
    for (int idx = tid; idx < 4096; idx += NTHREADS)
        su[idx >> 6][idx & 63] *= sinv[idx >> 6];
    __syncthreads();
    int i = tid & 63, cgp = tid >> 6;
    for (int j = 0; j < 64; j++) {
        float aij = sa[i][j];
        for (int c = cgp; c < 64; c += NTHREADS / 64)
            if (c > j) sa[i][c] -= aij * su[j][c];
        __syncthreads();
    }
    for (int idx = tid; idx < 4096; idx += NTHREADS) {
        int r = idx >> 6, j = idx & 63;
        d_J[(size_t)(r0 + r) * LDA + k + j] = sa[r][j] * sinv[j];
    }
}

/* ---------- U12 tile = L11^{-1} * A12 ---------- */
__device__ void trsm_col(int k, int c0, SM* sm)
{
    float (*sl)[65] = sm->trsm.su;
    float (*sa)[65] = sm->trsm.sa;
    int tid = threadIdx.x;
    __syncthreads();
    for (int idx = tid; idx < 4096; idx += NTHREADS) {
        int i = idx >> 6, j = idx & 63;
        sl[i][j] = d_J[(size_t)(k + i) * LDA + k + j];
        sa[i][j] = d_J[(size_t)(k + i) * LDA + c0 + j];
    }
    __syncthreads();
    int c = tid & 63, rg = tid >> 6;
    for (int j = 0; j < 64; j++) {
        float ajc = sa[j][c];
        for (int i2 = rg; i2 < 64; i2 += NTHREADS / 64)
            if (i2 > j) sa[i2][c] -= sl[i2][j] * ajc;
        __syncthreads();
    }
    for (int idx = tid; idx < 4096; idx += NTHREADS)
        d_J[(size_t)(k + (idx >> 6)) * LDA + c0 + (idx & 63)] = sa[idx >> 6][idx & 63];
}

/* ---------- small trailing tile: 64 rows x NCOLS cols, K=64 ---------- */
template <int NCOLS>
__device__ void gemm_block64(int k, int row0, int col0, SM* sm)
{
    const int tid = threadIdx.x;
    float (*A)[65]  = sm->g64.A;
    float (*B)[132] = sm->g64.B;
    __syncthreads();
    for (int idx = tid; idx < 4096; idx += NTHREADS) {
        int r = idx >> 6, c = idx & 63;
        A[c][r] = d_J[(size_t)(k + 64 + row0 + r) * LDA + k + c];
    }
    for (int idx = tid; idx < 64 * NCOLS; idx += NTHREADS) {
        int kk = idx / NCOLS, c = idx % NCOLS;
        B[kk][c] = d_J[(size_t)(k + kk) * LDA + (k + 64 + col0 + c)];
    }
    __syncthreads();
    constexpr int W = NCOLS / 16;
    const int rp = (tid >> 4) * 2;
    const int ct = (tid & 15) * W;
    float acc0[W], acc1[W];
#pragma unroll
    for (int v = 0; v < W; v++) { acc0[v] = 0.f; acc1[v] = 0.f; }
    for (int kk = 0; kk < 64; kk++) {
        float a0 = A[kk][rp], a1 = A[kk][rp + 1];
#pragma unroll
        for (int v = 0; v < W; v++) {
            float b = B[kk][ct + v];
            acc0[v] += a0 * b;
            acc1[v] += a1 * b;
        }
    }
    size_t base = (size_t)(k + 64 + row0 + rp) * LDA + (k + 64 + col0 + ct);
#pragma unroll
    for (int v = 0; v < W; v++) {
        d_J[base + v]       -= acc0[v];
        d_J[base + LDA + v] -= acc1[v];
    }
}

/* ---------- trailing update tile: 128x128, K=64, f32x2, double-buffered ---------- */
__device__ void gemm_tile(int k, int m, int row0, int col0, SM* sm)
{
    const int k2 = k + 64;
    const int tid = threadIdx.x;
    const int ty = tid >> 5;
    const int tx = tid & 31;
    const int ai = tid >> 2;
    const int aj = (tid & 3) << 2;
    const int bk = tid >> 5;
    const int bc = (tid & 31) << 2;
    const bool arow_ok = (row0 + ai) < m;
    const bool bcol_ok = (col0 + bc) < m;
    const float* gA = &d_J[(size_t)(k2 + row0 + ai) * LDA + k + aj];
    const float* gB = &d_J[(size_t)(k + bk) * LDA + k2 + col0 + bc];

    unsigned long long acc[4][4];
#pragma unroll
    for (int u = 0; u < 4; u++)
#pragma unroll
        for (int v = 0; v < 4; v++) acc[u][v] = 0ull;

    float4 z4 = make_float4(0.f, 0.f, 0.f, 0.f);
    float4 ra = arow_ok ? *(const float4*)gA : z4;
    float4 rb = bcol_ok ? *(const float4*)gB : z4;

    __syncthreads();
    sm->gemm.As[0][aj + 0][ai] = ra.x;
    sm->gemm.As[0][aj + 1][ai] = ra.y;
    sm->gemm.As[0][aj + 2][ai] = ra.z;
    sm->gemm.As[0][aj + 3][ai] = ra.w;
    *(float4*)&sm->gemm.Bs[0][bk][bc] = rb;
    __syncthreads();

    for (int c = 0; c < 4; c++) {
        const int cur = c & 1;
        float4 na, nb;
        if (c < 3) {
            na = arow_ok ? *(const float4*)(gA + (c + 1) * 16) : z4;
            nb = bcol_ok ? *(const float4*)(gB + (size_t)(c + 1) * 16 * LDA) : z4;
        }
#pragma unroll
        for (int kk = 0; kk < 16; kk++) {
            const unsigned long long* ap =
                (const unsigned long long*)&sm->gemm.As[cur][kk][ty * 8];
            unsigned long long a0 = ap[0], a1 = ap[1], a2 = ap[2], a3 = ap[3];
            float4 bv = *(const float4*)&sm->gemm.Bs[cur][kk][tx * 4];
            unsigned long long b0 = pk2(bv.x), b1 = pk2(bv.y),
                               b2 = pk2(bv.z), b3 = pk2(bv.w);
            fma2(acc[0][0], a0, b0); fma2(acc[0][1], a0, b1);
            fma2(acc[0][2], a0, b2); fma2(acc[0][3], a0, b3);
            fma2(acc[1][0], a1, b0); fma2(acc[1][1], a1, b1);
            fma2(acc[1][2], a1, b2); fma2(acc[1][3], a1, b3);
            fma2(acc[2][0], a2, b0); fma2(acc[2][1], a2, b1);
            fma2(acc[2][2], a2, b2); fma2(acc[2][3], a2, b3);
            fma2(acc[3][0], a3, b0); fma2(acc[3][1], a3, b1);
            fma2(acc[3][2], a3, b2); fma2(acc[3][3], a3, b3);
        }
        if (c < 3) {
            const int nxt = cur ^ 1;
            sm->gemm.As[nxt][aj + 0][ai] = na.x;
            sm->gemm.As[nxt][aj + 1][ai] = na.y;
            sm->gemm.As[nxt][aj + 2][ai] = na.z;
            sm->gemm.As[nxt][aj + 3][ai] = na.w;
            *(float4*)&sm->gemm.Bs[nxt][bk][bc] = nb;
        }
        __syncthreads();
    }

#pragma unroll
    for (int u = 0; u < 4; u++) {
        int r0 = row0 + ty * 8 + u * 2;
        if (r0 < m && (col0 + tx * 4) < m) {
            float2 p0 = upk(acc[u][0]), p1 = upk(acc[u][1]);
            float2 p2 = upk(acc[u][2]), p3 = upk(acc[u][3]);
            float4* c0 = (float4*)&d_J[(size_t)(k2 + r0) * LDA + k2 + col0 + tx * 4];
            float4 v0 = *c0;
            v0.x -= p0.x; v0.y -= p1.x; v0.z -= p2.x; v0.w -= p3.x;
            *c0 = v0;
            float4* c1 = (float4*)&d_J[(size_t)(k2 + r0 + 1) * LDA + k2 + col0 + tx * 4];
            float4 v1 = *c1;
            v1.x -= p0.y; v1.y -= p1.y; v1.z -= p2.y; v1.w -= p3.y;
            *c1 = v1;
        }
    }
}

/* ---------- forward y-update: y[r0..r1) -= L21(rows) . y_k (64-wide) ---------- */
__device__ __forceinline__ void y_update_range(int k, int r0, int r1)
{
    const int warp = threadIdx.x >> 5, lane = threadIdx.x & 31;
    const float ylo = d_y[k + lane];
    const float yhi = d_y[k + 32 + lane];
    for (int r = r0 + warp; r < r1; r += NWARPS) {
        const float* row = &d_J[(size_t)r * LDA + k];
        float s = row[lane] * ylo + row[lane + 32] * yhi;
#pragma unroll
        for (int o = 16; o; o >>= 1) s += __shfl_down_sync(0xffffffffu, s, o);
        if (lane == 0) d_y[r] -= s;
    }
}

/* ---------- invert 128x128 U diag block -> d_Uinv[bi]; optional y apply ---------- */
__device__ void invert_u128(int bi, bool apply, SM* sm)
{
    const int k = bi * 128;
    float (*U)[129] = sm->sub.m;
    float (*X)[129] = sm->sub.x2;
    const int t = threadIdx.x, warp = t >> 5, lane = t & 31;
    __syncthreads();
    for (int idx = t; idx < 128 * 128; idx += NTHREADS) {
        U[idx >> 7][idx & 127] = d_J[(size_t)(k + (idx >> 7)) * LDA + k + (idx & 127)];
        X[idx >> 7][idx & 127] = 0.f;
    }
    __syncthreads();
    if (t < 128) {
        int c = t;
        X[c][c] = 1.f / U[c][c];
        for (int j = c - 1; j >= 0; j--) {
            float acc = 0.f;
#pragma unroll 4
            for (int i = j + 1; i <= c; i++) acc += U[j][i] * X[i][c];
            X[j][c] = -acc / U[j][j];
        }
    }
    __syncthreads();
    for (int idx = t; idx < 128 * 128; idx += NTHREADS)
        d_Uinv[bi][idx] = X[idx >> 7][idx & 127];
    if (apply) {
        if (t < 128) sm->sub.val[t] = d_y[k + t];
        __syncthreads();
        for (int r = warp; r < 128; r += NWARPS) {
            float s = 0.f;
            for (int c2 = lane; c2 < 128; c2 += 32) s += X[r][c2] * sm->sub.val[c2];
#pragma unroll
            for (int o = 16; o; o >>= 1) s += __shfl_down_sync(0xffffffffu, s, o);
            if (lane == 0) d_y[k + r] = s;
        }
    }
    __syncthreads();
}

/* ---------- invert 128x128 unit-L diag block -> d_Linv[bi] ---------- */
__device__ void invert_l128(int bi, SM* sm)
{
    const int k = bi * 128;
    float (*L)[129] = sm->sub.m;
    float (*X)[129] = sm->sub.x2;
    const int t = threadIdx.x;
    __syncthreads();
    for (int idx = t; idx < 128 * 128; idx += NTHREADS) {
        L[idx >> 7][idx & 127] = d_J[(size_t)(k + (idx >> 7)) * LDA + k + (idx & 127)];
        X[idx >> 7][idx & 127] = 0.f;
    }
    __syncthreads();
    if (t < 128) {
        int c = t;
        X[c][c] = 1.f;
        for (int j = c + 1; j < 128; j++) {
            float acc = 0.f;
#pragma unroll 4
            for (int i = c; i < j; i++) acc += L[j][i] * X[i][c];
            X[j][c] = -acc;
        }
    }
    __syncthreads();
    for (int idx = t; idx < 128 * 128; idx += NTHREADS)
        d_Linv[bi][idx] = X[idx >> 7][idx & 127];
    __syncthreads();
}

/* ---------- y[k..k+128) = M * y[k..k+128), M dense 128x128 in global ---------- */
__device__ void apply_inv_gl(const float* __restrict__ M, int k, SM* sm)
{
    const int t = threadIdx.x, warp = t >> 5, lane = t & 31;
    __syncthreads();
    if (t < 128) sm->sub.val[t] = d_y[k + t];
    __syncthreads();
    float res[8];
#pragma unroll
    for (int rr = 0; rr < 8; rr++) {
        int r = warp * 8 + rr;
        const float* row = &M[r * 128];
        float s = row[lane] * sm->sub.val[lane]
                + row[lane + 32] * sm->sub.val[lane + 32]
                + row[lane + 64] * sm->sub.val[lane + 64]
                + row[lane + 96] * sm->sub.val[lane + 96];
#pragma unroll
        for (int o = 16; o; o >>= 1) s += __shfl_down_sync(0xffffffffu, s, o);
        res[rr] = s;
    }
    __syncthreads();
    if (lane == 0)
#pragma unroll
        for (int rr = 0; rr < 8; rr++) d_y[k + warp * 8 + rr] = res[rr];
    __syncthreads();
}

/* ---------- one 128-wide dot for substitution row update ---------- */
__device__ __forceinline__ void row_update(int r, int k, const float* yc, int lane)
{
    const float* row = &d_J[(size_t)r * LDA + k];
    float s = row[lane] * yc[lane] + row[lane + 32] * yc[lane + 32]
            + row[lane + 64] * yc[lane + 64] + row[lane + 96] * yc[lane + 96];
#pragma unroll
    for (int o = 16; o; o >>= 1) s += __shfl_down_sync(0xffffffffu, s, o);
    if (lane == 0) d_y[r] -= s;
}

/* ---------- RHS value for row i ---------- */
__device__ __forceinline__ float rhs_val(const Params& P, int i)
{
    if (i < NB) {
        float vm = d_x[NB + i];
        return (P.bt[i] == 3) ? d_x[i]
                              : (P.p_spec[i] - (d_Pacc[i] + vm * vm * P.gs[i]));
    } else if (i < DIM) {
        int ib = i - NB;
        float vm = d_x[i];
        return (P.bt[ib] >= 2) ? (vm - P.vmset[ib])
                               : (P.q_spec[ib] - (d_Qacc[ib] - vm * vm * P.bs[ib]));
    }
    return 0.f;
}

#define GSYNC() do { gen++; gsync(gen); } while (0)

/* =======================================================================
 *  The one persistent kernel
 * ======================================================================= */
__global__ void __launch_bounds__(NTHREADS, 1) solver_kernel(Params P)
{
    extern __shared__ char s_raw[];
    SM* sm = (SM*)s_raw;
    __shared__ int s_job;
    const int tid = threadIdx.x;
    const int gsize = gridDim.x * NTHREADS;
    const int gtid = blockIdx.x * NTHREADS + tid;
    const int warp = tid >> 5, lane = tid & 31;
    unsigned gen = 0;

    /* init: state, masks, flags, tickets, zero J+accs for step 0 */
    for (int i = gtid; i < DIMP; i += gsize) {
        d_x[i] = (i < DIM) ? P.x_in[i] : 0.0f;
        if (i < NB) {
            int b = P.bt[i];
            d_kp[i] = (b == 3) ? 0.f : 1.f;
            d_kq[i] = (b >= 2) ? 0.f : 1.f;
        }
        if (i < 64) { d_rowflag[i] = 0u; d_colflag[i] = 0u; d_ticket[i] = 0u; }
    }
    {
        size_t tot = (size_t)DIMP * LDA / 4;
        float4 z = make_float4(0.f, 0.f, 0.f, 0.f);
        for (size_t i = gtid; i < tot; i += gsize) ((float4*)d_J)[i] = z;
        for (int i = gtid; i < NB; i += gsize) { d_Pacc[i] = 0.f; d_Qacc[i] = 0.f; }
    }
    GSYNC();

    for (int t5 = 0; t5 < TSTEPS; t5++) {
        const bool do_factor = (t5 < NFACT);

        if (do_factor) {
            /* ---- assembly: edges (flows + J) + diag adds + padding ---- */
            for (int e = gtid; e < NE; e += gsize) {
                int s = P.ei[e], d = P.ei[NE + e];
                float vm_s = d_x[NB + s], vm_d = d_x[NB + d];
                float r = P.br_r[e], xx = P.br_x[e];
                float den = r * r + xx * xx;
                float g = r / den, b = -xx / den;
                float tp = P.tap[e];
                float th = d_x[s] - d_x[d];
                float sf, cf;
                sincosf(th - P.shift[e], &sf, &cf);
                float ct = cf, st = -sf;
                float vi_t = vm_s / tp;
                float vij = vm_s * vm_d / tp;

                float gfr = P.g_fr[e], bfr = P.b_fr[e], gto = P.g_to[e], bto = P.b_to[e];
                float Pf = vi_t * vi_t * (g + gfr) + vij * (-g * cf - b * sf);
                float Qf = -vi_t * vi_t * (b + bfr) + vij * (-g * sf + b * cf);
                float Pt = vm_d * vm_d * (g + gto) + vij * (-g * ct - b * st);
                float Qt = -vm_d * vm_d * (b + bto) + vij * (-g * st + b * ct);
                atomicAdd(&d_Pacc[s], Pf); atomicAdd(&d_Pacc[d], Pt);
                atomicAdd(&d_Qacc[s], Qf); atomicAdd(&d_Qacc[d], Qt);

                float Af = g * cf + b * sf, Bf = g * sf - b * cf;
                float At = g * ct + b * st, Bt = g * st - b * ct;
                size_t Rs  = (size_t)s * LDA, Rd = (size_t)d * LDA;
                size_t Rqs = (size_t)(NB + s) * LDA, Rqd = (size_t)(NB + d) * LDA;

                if (d_kp[s] != 0.f) {
                    atomicAdd(&d_J[Rs + s],      -vij * Bf);
                    atomicAdd(&d_J[Rs + d],       vij * Bf);
                    atomicAdd(&d_J[Rs + NB + s], -(2.f * vm_s / (tp * tp) * (g + gfr) - vm_d / tp * Af));
                    atomicAdd(&d_J[Rs + NB + d],  (vm_s / tp) * Af);
                }
                if (d_kp[d] != 0.f) {
                    atomicAdd(&d_J[Rd + d],      -vij * Bt);
                    atomicAdd(&d_J[Rd + s],       vij * Bt);
                    atomicAdd(&d_J[Rd + NB + d], -(2.f * vm_d * (g + gto) - vm_s / tp * At));
                    atomicAdd(&d_J[Rd + NB + s],  (vm_d / tp) * At);
                }
                if (d_kq[s] != 0.f) {
                    atomicAdd(&d_J[Rqs + s],      vij * Af);
                    atomicAdd(&d_J[Rqs + d],     -vij * Af);
                    atomicAdd(&d_J[Rqs + NB + s], (2.f * vm_s / (tp * tp) * (b + bfr) + vm_d / tp * Bf));
                    atomicAdd(&d_J[Rqs + NB + d], (vm_s / tp) * Bf);
                }
                if (d_kq[d] != 0.f) {
                    atomicAdd(&d_J[Rqd + d],      vij * At);
                    atomicAdd(&d_J[Rqd + s],     -vij * At);
                    atomicAdd(&d_J[Rqd + NB + d], (2.f * vm_d * (b + bto) + vm_s / tp * Bt));
                    atomicAdd(&d_J[Rqd + NB + s], (vm_s / tp) * Bt);
                }
            }
            for (int i = gtid; i < NB; i += gsize) {
                int b = P.bt[i];
                float vm = d_x[NB + i];
                atomicAdd(&d_J[(size_t)i * LDA + i], ((b == 3) ? 1.f : 0.f) + EPSJ);
                atomicAdd(&d_J[(size_t)i * LDA + NB + i], d_kp[i] * (-2.f * vm * P.gs[i]));
                atomicAdd(&d_J[(size_t)(NB + i) * LDA + (NB + i)],
                          d_kq[i] * (2.f * vm * P.bs[i]) + ((b >= 2) ? 1.f : 0.f) + EPSJ);
            }
            for (int i = DIM + gtid; i < DIMP; i += gsize)
                d_J[(size_t)i * LDA + i] = 1.0f;
            GSYNC();

            /* ---- RHS + lu_diag(0); reset ticket[0] ---- */
            if (blockIdx.x == 0) {
                if (tid == 0) d_ticket[0] = 0u;
                if (tid < 64) d_y[tid] = rhs_val(P, tid);
                __syncthreads();
                lu_diag(0, sm);
            } else {
                for (int i = 64 + (blockIdx.x - 1) * NTHREADS + tid; i < DIMP;
                     i += (gridDim.x - 1) * NTHREADS)
                    d_y[i] = rhs_val(P, i);
            }
            GSYNC();

            /* ---- blocked LU (fwd subst folded), ticket pool ---- */
            for (int k = 0; k + 64 < DIMP; k += 64) {
                const int m = DIMP - k - 64;
                const int ntr = m / 64;
                const int g = (m + 127) / 128;
                const int kp = k >> 6;
                const unsigned epoch = (unsigned)(t5 * 64 + kp + 1);
                const int bid = blockIdx.x;

                if (bid == 0) {
                    if (tid == 0) {
                        d_ticket[kp + 1] = 0u;
                        wait_flag(&d_rowflag[0], epoch);
                        wait_flag(&d_colflag[0], epoch);
                        __threadfence();
                    }
                    __syncthreads();
                    y_update_range(k, k + 64, k + 128);
                    gemm_block64<64>(k, 0, 0, sm);
                    lu_diag(k + 64, sm);
                } else {
                    for (int j = bid - 1; j < 2 * ntr; j += gridDim.x - 1) {
                        if (j < ntr) {
                            trsm_row(k, k + 64 + j * 64, sm);
                            __syncthreads();
                            if (tid == 0) { __threadfence(); d_rowflag[j] = epoch; }
                        } else {
                            int i2 = j - ntr;
                            trsm_col(k, k + 64 + i2 * 64, sm);
                            __syncthreads();
                            if (tid == 0) { __threadfence(); d_colflag[i2] = epoch; }
                        }
                    }
                    const int nq = (m >= 128) ? 2 : 0;
                    const int nyj = ntr - 1;
                    const int njobs = nq + nyj + g * g - 1;
                    for (;;) {
                        __syncthreads();
                        if (tid == 0) s_job = (int)atomicAdd(&d_ticket[kp], 1u);
                        __syncthreads();
                        const int job = s_job;
                        if (job >= njobs) break;
                        if (job < nq) {
                            if (job == 0) {
                                if (tid == 0) {
                                    wait_flag(&d_rowflag[1], epoch);
                                    wait_flag(&d_colflag[0], epoch);
                                    wait_flag(&d_colflag[1], epoch);
                                    __threadfence();
                                }
                                __syncthreads();
                                gemm_block64<128>(k, 64, 0, sm);
                            } else {
                                if (tid == 0) {
                                    wait_flag(&d_rowflag[0], epoch);
                                    wait_flag(&d_colflag[1], epoch);
                                    __threadfence();
                                }
                                __syncthreads();
                                gemm_block64<64>(k, 0, 64, sm);
                            }
                        } else if (job < nq + nyj) {
                            int rt = job - nq + 1;
                            if (tid == 0) { wait_flag(&d_rowflag[rt], epoch); __threadfence(); }
                            __syncthreads();
                            int r0 = k + 64 + rt * 64;
                            y_update_range(k, r0, r0 + 64);
                        } else {
                            int t2 = job - nq - nyj + 1;
                            int r = t2 / g, c = t2 % g;
                            if (tid == 0) {
                                wait_flag(&d_rowflag[2 * r], epoch);
                                if (2 * r + 1 < ntr) wait_flag(&d_rowflag[2 * r + 1], epoch);
                                wait_flag(&d_colflag[2 * c], epoch);
                                if (2 * c + 1 < ntr) wait_flag(&d_colflag[2 * c + 1], epoch);
                                __threadfence();
                            }
                            __syncthreads();
                            gemm_tile(k, m, r * 128, c * 128, sm);
                        }
                    }
                }
                GSYNC();
            }

            /* ---- one-time: invert all 128-diag blocks (U and unit-L);
             *      block 31 also applies Uinv to the last panel's y ---- */
            if (blockIdx.x < 32) invert_u128(blockIdx.x, blockIdx.x == 31, sm);
            else if (blockIdx.x < 64) invert_l128(blockIdx.x - 32, sm);
            GSYNC();
        } else {
            /* ======== substitution-only step: reuse stored LU ======== */
            for (int e = gtid; e < NE; e += gsize) {
                int s = P.ei[e], d = P.ei[NE + e];
                float vm_s = d_x[NB + s], vm_d = d_x[NB + d];
                float r = P.br_r[e], xx = P.br_x[e];
                float den = r * r + xx * xx;
                float g = r / den, b = -xx / den;
                float tp = P.tap[e];
                float th = d_x[s] - d_x[d];
                float sf, cf;
                sincosf(th - P.shift[e], &sf, &cf);
                float ct = cf, st = -sf;
                float vi_t = vm_s / tp;
                float vij = vm_s * vm_d / tp;
                float Pf = vi_t * vi_t * (g + P.g_fr[e]) + vij * (-g * cf - b * sf);
                float Qf = -vi_t * vi_t * (b + P.b_fr[e]) + vij * (-g * sf + b * cf);
                float Pt = vm_d * vm_d * (g + P.g_to[e]) + vij * (-g * ct - b * st);
                float Qt = -vm_d * vm_d * (b + P.b_to[e]) + vij * (-g * st + b * ct);
                atomicAdd(&d_Pacc[s], Pf); atomicAdd(&d_Pacc[d], Pt);
                atomicAdd(&d_Qacc[s], Qf); atomicAdd(&d_Qacc[d], Qt);
            }
            GSYNC();

            /* RHS + first fwd diag apply */
            if (blockIdx.x == 0) {
                if (tid < PW) d_y[tid] = rhs_val(P, tid);
                __syncthreads();
                apply_inv_gl(d_Linv[0], 0, sm);
            } else {
                for (int i = PW + (blockIdx.x - 1) * NTHREADS + tid; i < DIMP;
                     i += (gridDim.x - 1) * NTHREADS)
                    d_y[i] = rhs_val(P, i);
            }
            GSYNC();

            /* forward substitution, 128-wide panels, block-0 lookahead.
             * Remote rows capped at DIM: padding rows have zero L entries. */
            for (int k = 0; k + PW < DIMP; k += PW) {
                __syncthreads();
                if (tid < PW) sm->sub.yc[tid] = d_y[k + tid];
                __syncthreads();
                if (blockIdx.x == 0) {
                    for (int r = k + PW + warp; r < k + 2 * PW; r += NWARPS)
                        row_update(r, k, sm->sub.yc, lane);
                    __syncthreads();
                    apply_inv_gl(d_Linv[(k + PW) >> 7], k + PW, sm);
                    if (k == DIMP - 2 * PW)
                        apply_inv_gl(d_Uinv[(k + PW) >> 7], k + PW, sm);
                } else {
                    int gw = (blockIdx.x - 1) * NWARPS + warp;
                    int tot = (gridDim.x - 1) * NWARPS;
                    for (int r = k + 2 * PW + gw; r < DIM; r += tot)
                        row_update(r, k, sm->sub.yc, lane);
                }
                GSYNC();
            }
        }
        /* d_y = L^{-1} F; last U-diag panel already applied */

        /* ---- backward substitution; Newton update merged into last phase ---- */
        for (int k = DIMP - PW; k > 0; k -= PW) {
            __syncthreads();
            if (tid < PW) sm->sub.yc[tid] = d_y[k + tid];
            __syncthreads();
            if (blockIdx.x == 0) {
                for (int r = k - PW + warp; r < k; r += NWARPS)
                    row_update(r, k, sm->sub.yc, lane);
                __syncthreads();
                apply_inv_gl(d_Uinv[(k - PW) >> 7], k - PW, sm);
                if (k == PW) {
                    /* Newton for i in [0, PW): all < NB, no clip needed */
                    for (int i = tid; i < PW; i += NTHREADS)
                        d_x[i] = d_x[i] - d_y[i];
                }
            } else {
                int gw = (blockIdx.x - 1) * NWARPS + warp;
                int tot = (gridDim.x - 1) * NWARPS;
                for (int r = gw; r < k - PW; r += tot)
                    row_update(r, k, sm->sub.yc, lane);
                if (k == PW) {
                    /* Newton for i in [PW, DIM): y final for panels >= 1 */
                    for (int i = PW + (blockIdx.x - 1) * NTHREADS + tid; i < DIM;
                         i += (gridDim.x - 1) * NTHREADS) {
                        float v = d_x[i] - d_y[i];
                        if (i >= NB) v = fminf(fmaxf(v, 0.5f), 1.5f);
                        d_x[i] = v;
                    }
                    if (t5 < TSTEPS - 1)
                        for (int i = (blockIdx.x - 1) * NTHREADS + tid; i < NB;
                             i += (gridDim.x - 1) * NTHREADS) {
                            d_Pacc[i] = 0.f; d_Qacc[i] = 0.f;
                        }
                }
            }
            GSYNC();
        }
    }

    for (int i = gtid; i < DIM; i += gsize)
        P.out[i] = d_x[i];
}

extern "C" void kernel_launch(void* const* d_in, const int* in_sizes, int n_in,
                              void* d_out, int out_size)
{
    Params P;
    P.x_in   = (const float*)d_in[0];
    P.ei     = (const int*)  d_in[1];
    P.br_r   = (const float*)d_in[2];
    P.br_x   = (const float*)d_in[3];
    P.g_fr   = (const float*)d_in[4];
    P.b_fr   = (const float*)d_in[5];
    P.g_to   = (const float*)d_in[6];
    P.b_to   = (const float*)d_in[7];
    P.tap    = (const float*)d_in[8];
    P.shift  = (const float*)d_in[9];
    P.p_spec = (const float*)d_in[10];
    P.q_spec = (const float*)d_in[11];
    P.gs     = (const float*)d_in[12];
    P.bs     = (const float*)d_in[13];
    P.bt     = (const int*)  d_in[14];
    P.vmset  = (const float*)d_in[15];
    P.out    = (float*)d_out;

    cudaFuncSetAttribute(solver_kernel,
                         cudaFuncAttributeMaxDynamicSharedMemorySize,
                         (int)SMEM_BYTES);

    int dev = 0, nsm = 0, per_sm = 0;
    cudaGetDevice(&dev);
    cudaDeviceGetAttribute(&nsm, cudaDevAttrMultiProcessorCount, dev);
    cudaOccupancyMaxActiveBlocksPerMultiprocessor(&per_sm, solver_kernel,
                                                  NTHREADS, SMEM_BYTES);
    if (per_sm < 1) per_sm = 1;
    int grid = nsm * per_sm;
    if (grid < 64) grid = 64;
    if (grid > 1024) grid = 1024;

    solver_kernel<<<grid, NTHREADS, SMEM_BYTES>>>(P);
}